// round 1
// baseline (speedup 1.0000x reference)
#include <cuda_runtime.h>
#include <math.h>

#define NTILES 8
#define DP 64
#define DC 1024
#define DH 4096
#define BATCH 16
#define SEQLEN 512
#define NTOK (BATCH*SEQLEN)

#define BM 128
#define BN 128
#define BK 8

// Scratch (allocation-free rule: __device__ globals)
__device__ int   g_count[NTILES];
__device__ int   g_tokens[NTILES][NTOK];
__device__ float g_hidden[(size_t)NTOK * DH];   // 128 MB

__global__ void zero_counts_kernel() {
    if (threadIdx.x < NTILES) g_count[threadIdx.x] = 0;
}

// One block (128 threads) per token: compute 8 scores, argmax (first-max wins,
// matching jnp.argmax), append token to its tile's list.
__global__ void route_kernel(const float* __restrict__ x,
                             const float* __restrict__ pe,
                             const float* __restrict__ pw_p,
                             const float* __restrict__ cw_p,
                             const float* __restrict__ pos_sigs,
                             const float* __restrict__ content_sigs)
{
    __shared__ float s_csig[NTILES][DC];
    __shared__ float s_psig[NTILES][DP];
    __shared__ float s_red[NTILES][128];

    const int tid = threadIdx.x;
    const int tok = blockIdx.x;
    const int s   = tok % SEQLEN;

    for (int i = tid; i < NTILES * DC; i += 128) {
        float v = content_sigs[i];
        (&s_csig[0][0])[i] = (v > 0.f) ? 1.f : ((v < 0.f) ? -1.f : 0.f);
    }
    for (int i = tid; i < NTILES * DP; i += 128) {
        float v = pos_sigs[i];
        (&s_psig[0][0])[i] = (v > 0.f) ? 1.f : ((v < 0.f) ? -1.f : 0.f);
    }
    __syncthreads();

    float pw = 1.f / (1.f + expf(-pw_p[0]));
    float cw = 1.f / (1.f + expf(-cw_p[0]));
    float tot = pw + cw;
    pw /= tot; cw /= tot;

    float accc[NTILES], accp[NTILES];
#pragma unroll
    for (int t = 0; t < NTILES; t++) { accc[t] = 0.f; accp[t] = 0.f; }

    const float* xr = x + (size_t)tok * DC;
    for (int d = tid; d < DC; d += 128) {
        float xv = xr[d];
#pragma unroll
        for (int t = 0; t < NTILES; t++) accc[t] += xv * s_csig[t][d];
    }
    const float* per = pe + (size_t)s * DP;
    for (int d = tid; d < DP; d += 128) {
        float pv = per[d];
#pragma unroll
        for (int t = 0; t < NTILES; t++) accp[t] += pv * s_psig[t][d];
    }
#pragma unroll
    for (int t = 0; t < NTILES; t++) s_red[t][tid] = cw * accc[t] + pw * accp[t];
    __syncthreads();

    if (tid == 0) {
        int best = 0; float bv = -3.0e38f;
        for (int t = 0; t < NTILES; t++) {
            float sum = 0.f;
            for (int i = 0; i < 128; i++) sum += s_red[t][i];
            if (sum > bv) { bv = sum; best = t; }   // strict > -> first max wins
        }
        int pos = atomicAdd(&g_count[best], 1);
        g_tokens[best][pos] = tok;
    }
}

__device__ __forceinline__ float gelu_exact(float v) {
    return 0.5f * v * (1.0f + erff(v * 0.70710678118654752f));
}

// Grouped SGEMM1: H[tok] = gelu(x[tok] @ W1[tile] + b1[tile]) for tokens of each tile.
__global__ __launch_bounds__(256, 2)
void gemm1_kernel(const float* __restrict__ x,
                  const float* __restrict__ W1,
                  const float* __restrict__ b1)
{
    const int t     = blockIdx.z;
    const int count = g_count[t];
    const int m0    = blockIdx.y * BM;
    if (m0 >= count) return;
    const int n0    = blockIdx.x * BN;

    const float* B = W1 + (size_t)t * DC * DH;   // [DC][DH] row-major

    __shared__ float As[BK][BM];
    __shared__ float Bs[BK][BN];

    const int tid = threadIdx.x;
    const int tx  = tid & 15;   // 16 cols of threads
    const int ty  = tid >> 4;   // 16 rows of threads

    // A load: 2 threads per row, float4 along k
    const int a_m = tid >> 1;
    const int a_k = (tid & 1) * 4;
    const int arow = m0 + a_m;
    const float* a_ptr = nullptr;
    if (arow < count) {
        int tokA = g_tokens[t][arow];
        a_ptr = x + (size_t)tokA * DC + a_k;
    }
    // B load: float4 along n
    const int b_k = tid >> 5;          // 0..7
    const int b_n = (tid & 31) * 4;    // 0..124
    const float* b_ptr = B + (size_t)b_k * DH + n0 + b_n;

    float acc[8][8];
#pragma unroll
    for (int i = 0; i < 8; i++)
#pragma unroll
        for (int j = 0; j < 8; j++) acc[i][j] = 0.f;

    for (int kb = 0; kb < DC; kb += BK) {
        float4 av = make_float4(0.f, 0.f, 0.f, 0.f);
        if (a_ptr) av = *(const float4*)(a_ptr + kb);
        As[a_k + 0][a_m] = av.x;
        As[a_k + 1][a_m] = av.y;
        As[a_k + 2][a_m] = av.z;
        As[a_k + 3][a_m] = av.w;
        *(float4*)&Bs[b_k][b_n] = *(const float4*)(b_ptr + (size_t)kb * DH);
        __syncthreads();
#pragma unroll
        for (int k = 0; k < BK; k++) {
            float a[8], b[8];
            *(float4*)&a[0] = *(const float4*)&As[k][ty * 8];
            *(float4*)&a[4] = *(const float4*)&As[k][ty * 8 + 4];
            *(float4*)&b[0] = *(const float4*)&Bs[k][tx * 8];
            *(float4*)&b[4] = *(const float4*)&Bs[k][tx * 8 + 4];
#pragma unroll
            for (int i = 0; i < 8; i++)
#pragma unroll
                for (int j = 0; j < 8; j++) acc[i][j] += a[i] * b[j];
        }
        __syncthreads();
    }

#pragma unroll
    for (int i = 0; i < 8; i++) {
        int m = m0 + ty * 8 + i;
        if (m < count) {
            int tok = g_tokens[t][m];
            float* hr = g_hidden + (size_t)tok * DH + n0 + tx * 8;
            const float* br = b1 + (size_t)t * DH + n0 + tx * 8;
#pragma unroll
            for (int j = 0; j < 8; j++) {
                float v = acc[i][j] + br[j];
                hr[j] = gelu_exact(v);
            }
        }
    }
}

// Grouped SGEMM2: out[tok] = H[tok] @ W2[tile] + b2[tile]
__global__ __launch_bounds__(256, 2)
void gemm2_kernel(const float* __restrict__ W2,
                  const float* __restrict__ b2,
                  float* __restrict__ out)
{
    const int t     = blockIdx.z;
    const int count = g_count[t];
    const int m0    = blockIdx.y * BM;
    if (m0 >= count) return;
    const int n0    = blockIdx.x * BN;

    const float* B = W2 + (size_t)t * DH * DC;   // [DH][DC] row-major

    __shared__ float As[BK][BM];
    __shared__ float Bs[BK][BN];

    const int tid = threadIdx.x;
    const int tx  = tid & 15;
    const int ty  = tid >> 4;

    const int a_m = tid >> 1;
    const int a_k = (tid & 1) * 4;
    const int arow = m0 + a_m;
    const float* a_ptr = nullptr;
    if (arow < count) {
        int tokA = g_tokens[t][arow];
        a_ptr = g_hidden + (size_t)tokA * DH + a_k;
    }
    const int b_k = tid >> 5;
    const int b_n = (tid & 31) * 4;
    const float* b_ptr = B + (size_t)b_k * DC + n0 + b_n;

    float acc[8][8];
#pragma unroll
    for (int i = 0; i < 8; i++)
#pragma unroll
        for (int j = 0; j < 8; j++) acc[i][j] = 0.f;

    for (int kb = 0; kb < DH; kb += BK) {
        float4 av = make_float4(0.f, 0.f, 0.f, 0.f);
        if (a_ptr) av = *(const float4*)(a_ptr + kb);
        As[a_k + 0][a_m] = av.x;
        As[a_k + 1][a_m] = av.y;
        As[a_k + 2][a_m] = av.z;
        As[a_k + 3][a_m] = av.w;
        *(float4*)&Bs[b_k][b_n] = *(const float4*)(b_ptr + (size_t)kb * DC);
        __syncthreads();
#pragma unroll
        for (int k = 0; k < BK; k++) {
            float a[8], b[8];
            *(float4*)&a[0] = *(const float4*)&As[k][ty * 8];
            *(float4*)&a[4] = *(const float4*)&As[k][ty * 8 + 4];
            *(float4*)&b[0] = *(const float4*)&Bs[k][tx * 8];
            *(float4*)&b[4] = *(const float4*)&Bs[k][tx * 8 + 4];
#pragma unroll
            for (int i = 0; i < 8; i++)
#pragma unroll
                for (int j = 0; j < 8; j++) acc[i][j] += a[i] * b[j];
        }
        __syncthreads();
    }

#pragma unroll
    for (int i = 0; i < 8; i++) {
        int m = m0 + ty * 8 + i;
        if (m < count) {
            int tok = g_tokens[t][m];
            float* orow = out + (size_t)tok * DC + n0 + tx * 8;
            const float* br = b2 + (size_t)t * DC + n0 + tx * 8;
#pragma unroll
            for (int j = 0; j < 8; j++) {
                orow[j] = acc[i][j] + br[j];
            }
        }
    }
}

extern "C" void kernel_launch(void* const* d_in, const int* in_sizes, int n_in,
                              void* d_out, int out_size)
{
    const float* x            = (const float*)d_in[0];
    const float* pe           = (const float*)d_in[1];
    const float* pw           = (const float*)d_in[2];
    const float* cw           = (const float*)d_in[3];
    const float* pos_sigs     = (const float*)d_in[4];
    const float* content_sigs = (const float*)d_in[5];
    const float* W1           = (const float*)d_in[6];
    const float* b1           = (const float*)d_in[7];
    const float* W2           = (const float*)d_in[8];
    const float* b2           = (const float*)d_in[9];
    float* out                = (float*)d_out;

    zero_counts_kernel<<<1, 32>>>();
    route_kernel<<<NTOK, 128>>>(x, pe, pw, cw, pos_sigs, content_sigs);

    dim3 g1(DH / BN, NTOK / BM, NTILES);   // (32, 64, 8); blocks past count exit
    gemm1_kernel<<<g1, 256>>>(x, W1, b1);

    dim3 g2(DC / BN, NTOK / BM, NTILES);   // (8, 64, 8)
    gemm2_kernel<<<g2, 256>>>(W2, b2, out);
}

// round 6
// speedup vs baseline: 4.5937x; 4.5937x over previous
#include <cuda_runtime.h>
#include <cuda_fp16.h>
#include <math.h>
#include <stdint.h>

#define NTILES 8
#define DP 64
#define DC 1024
#define DH 4096
#define BATCH 16
#define SEQLEN 512
#define NTOK (BATCH*SEQLEN)

// ---------------- device scratch (no allocations allowed) ----------------
__device__ int    g_count[NTILES];
__device__ int    g_tokens[NTILES][NTOK];
__device__ __align__(16) __half g_xh[(size_t)NTOK * DC];            // x in fp16
__device__ __align__(16) __half g_hid[(size_t)NTOK * DH];           // hidden fp16 (64MB)
__device__ __align__(16) __half g_w1h[(size_t)NTILES * DH * DC];    // W1^T fp16 [t][n][k]
__device__ __align__(16) __half g_w2h[(size_t)NTILES * DC * DH];    // W2^T fp16 [t][n][k]

// ---------------- PTX helpers (plain sm_103-legal ISA only) ----------------
__device__ __forceinline__ uint32_t smem_u32(const void* p) {
    uint32_t a;
    asm("{ .reg .u64 t; cvta.to.shared.u64 t, %1; cvt.u32.u64 %0, t; }" : "=r"(a) : "l"(p));
    return a;
}
__device__ __forceinline__ void cp_async16(uint32_t saddr, const void* gaddr) {
    asm volatile("cp.async.cg.shared.global [%0], [%1], 16;" :: "r"(saddr), "l"(gaddr) : "memory");
}
__device__ __forceinline__ void cp_commit() {
    asm volatile("cp.async.commit_group;" ::: "memory");
}
__device__ __forceinline__ void ldsm_x4(uint32_t* r, uint32_t addr) {
    asm volatile("ldmatrix.sync.aligned.m8n8.x4.shared.b16 {%0,%1,%2,%3}, [%4];"
                 : "=r"(r[0]), "=r"(r[1]), "=r"(r[2]), "=r"(r[3]) : "r"(addr));
}
__device__ __forceinline__ void mma16816(float* c, const uint32_t* a, uint32_t b0, uint32_t b1) {
    asm volatile(
        "mma.sync.aligned.m16n8k16.row.col.f32.f16.f16.f32 "
        "{%0,%1,%2,%3}, {%4,%5,%6,%7}, {%8,%9}, {%0,%1,%2,%3};"
        : "+f"(c[0]), "+f"(c[1]), "+f"(c[2]), "+f"(c[3])
        : "r"(a[0]), "r"(a[1]), "r"(a[2]), "r"(a[3]), "r"(b0), "r"(b1));
}

// ---------------- routing (unchanged, proven in R1) ----------------
__global__ void zero_counts_kernel() {
    if (threadIdx.x < NTILES) g_count[threadIdx.x] = 0;
}

__global__ void route_kernel(const float* __restrict__ x,
                             const float* __restrict__ pe,
                             const float* __restrict__ pw_p,
                             const float* __restrict__ cw_p,
                             const float* __restrict__ pos_sigs,
                             const float* __restrict__ content_sigs)
{
    __shared__ float s_csig[NTILES][DC];
    __shared__ float s_psig[NTILES][DP];
    __shared__ float s_red[NTILES][128];

    const int tid = threadIdx.x;
    const int tok = blockIdx.x;
    const int s   = tok % SEQLEN;

    for (int i = tid; i < NTILES * DC; i += 128) {
        float v = content_sigs[i];
        (&s_csig[0][0])[i] = (v > 0.f) ? 1.f : ((v < 0.f) ? -1.f : 0.f);
    }
    for (int i = tid; i < NTILES * DP; i += 128) {
        float v = pos_sigs[i];
        (&s_psig[0][0])[i] = (v > 0.f) ? 1.f : ((v < 0.f) ? -1.f : 0.f);
    }
    __syncthreads();

    float pw = 1.f / (1.f + expf(-pw_p[0]));
    float cw = 1.f / (1.f + expf(-cw_p[0]));
    float tot = pw + cw;
    pw /= tot; cw /= tot;

    float accc[NTILES], accp[NTILES];
#pragma unroll
    for (int t = 0; t < NTILES; t++) { accc[t] = 0.f; accp[t] = 0.f; }

    const float* xr = x + (size_t)tok * DC;
    for (int d = tid; d < DC; d += 128) {
        float xv = xr[d];
#pragma unroll
        for (int t = 0; t < NTILES; t++) accc[t] += xv * s_csig[t][d];
    }
    const float* per = pe + (size_t)s * DP;
    for (int d = tid; d < DP; d += 128) {
        float pv = per[d];
#pragma unroll
        for (int t = 0; t < NTILES; t++) accp[t] += pv * s_psig[t][d];
    }
#pragma unroll
    for (int t = 0; t < NTILES; t++) s_red[t][tid] = cw * accc[t] + pw * accp[t];
    __syncthreads();

    if (tid == 0) {
        int best = 0; float bv = -3.0e38f;
        for (int t = 0; t < NTILES; t++) {
            float sum = 0.f;
            for (int i = 0; i < 128; i++) sum += s_red[t][i];
            if (sum > bv) { bv = sum; best = t; }
        }
        int pos = atomicAdd(&g_count[best], 1);
        g_tokens[best][pos] = tok;
    }
}

__global__ void pad_tokens_kernel() {
    int t = blockIdx.x;
    int c = g_count[t];
    int pc = (c + 127) & ~127;
    for (int i = c + threadIdx.x; i < pc; i += blockDim.x) g_tokens[t][i] = 0;
}

// ---------------- conversions ----------------
__global__ void convert_x_kernel(const float* __restrict__ x)
{
    size_t i = ((size_t)blockIdx.x * blockDim.x + threadIdx.x) * 4;
    float4 v = *(const float4*)(x + i);
    __half2* o = (__half2*)(g_xh + i);
    o[0] = __floats2half2_rn(v.x, v.y);
    o[1] = __floats2half2_rn(v.z, v.w);
}

// src[t] is [R][C] fp32 row-major; dst[t][c][r] = fp16(src[t][r][c])
__global__ void convert_w_kernel(const float* __restrict__ src, int R, int C, int which)
{
    __half* dst = which ? g_w2h : g_w1h;
    __shared__ float ts[32][33];
    const int t = blockIdx.z;
    const float* S = src + (size_t)t * R * C;
    __half* D = dst + (size_t)t * R * C;
    const int c0 = blockIdx.x * 32, r0 = blockIdx.y * 32;
#pragma unroll
    for (int i = 0; i < 32; i += 8)
        ts[threadIdx.y + i][threadIdx.x] = S[(size_t)(r0 + threadIdx.y + i) * C + c0 + threadIdx.x];
    __syncthreads();
#pragma unroll
    for (int i = 0; i < 32; i += 8)
        D[(size_t)(c0 + threadIdx.y + i) * R + r0 + threadIdx.x] =
            __float2half_rn(ts[threadIdx.x][threadIdx.y + i]);
}

__device__ __forceinline__ float gelu_exact(float v) {
    return 0.5f * v * (1.0f + erff(v * 0.70710678118654752f));
}

// ---------------- grouped fp16 mma.sync GEMM ----------------
// Block tile 128(M) x 128(N), BK=32, 3-stage cp.async pipeline.
// A: gathered token rows (fp16, [tok][K]); B: weights fp16 [n][k] (K-major).
// Swizzle: 16B chunk c of row r stored at c ^ ((r>>1)&3)  -> LDSM conflict-free.
#define GG_SMEM (3 * 16384)

template <bool FIRST>
__global__ __launch_bounds__(256, 2)
void grouped_gemm(const float* __restrict__ bias, float* __restrict__ C_ext)
{
    const int KTOT = FIRST ? DC : DH;
    const int NTOT = FIRST ? DH : DC;
    const int NKB  = KTOT / 32;

    const int t     = blockIdx.z;
    const int count = g_count[t];
    const int m0    = blockIdx.y * 128;
    if (m0 >= count) return;
    const int n0    = blockIdx.x * 128;

    extern __shared__ __align__(128) char smem[];
    __shared__ int s_tok[128];
    const uint32_t sb = smem_u32(smem);

    const int tid  = threadIdx.x;
    const int wid  = tid >> 5;
    const int lane = tid & 31;
    const int warp_m = wid >> 1;   // 0..3  (rows 32*warp_m)
    const int warp_n = wid & 1;    // 0..1  (cols 64*warp_n)

    if (tid < 128) s_tok[tid] = g_tokens[t][m0 + tid];
    __syncthreads();

    const __half* A_src = FIRST ? g_xh : g_hid;
    const __half* Bt    = (FIRST ? g_w1h : g_w2h) + (size_t)t * NTOT * KTOT + (size_t)n0 * KTOT;
    const float*  bias_t = bias + (size_t)t * NTOT + n0;

    // ---- per-thread cp.async geometry: row = tid>>1, two 16B chunks ----
    const int ld_r  = tid >> 1;             // 0..127
    const int ld_c0 = (tid & 1) * 2;        // 0 or 2
    const uint32_t sw0 = (uint32_t)(ld_c0 ^ ((ld_r >> 1) & 3));
    const uint32_t a_soff0 = (uint32_t)(ld_r * 64) + sw0 * 16u;
    const uint32_t a_soff1 = a_soff0 ^ 16u;         // chunk c0+1 = c0^1
    const __half* a_row = A_src + (size_t)s_tok[ld_r] * KTOT;
    const __half* b_row = Bt + (size_t)ld_r * KTOT;

    // ---- ldmatrix geometry ----
    const int a_rin = lane & 15;
    const int a_hb  = lane >> 4;
    uint32_t a_off[2];
#pragma unroll
    for (int mt = 0; mt < 2; mt++) {
        int row = warp_m * 32 + mt * 16 + a_rin;
        a_off[mt] = (uint32_t)(row * 64) + (uint32_t)((a_hb ^ ((row >> 1) & 3)) * 16);
    }
    const int b_rin = (lane & 7) + ((lane >> 4) << 3);
    const int b_hb  = (lane >> 3) & 1;
    uint32_t b_off[4];
#pragma unroll
    for (int bt = 0; bt < 4; bt++) {
        int row = warp_n * 64 + bt * 16 + b_rin;
        b_off[bt] = (uint32_t)(row * 64) + (uint32_t)((b_hb ^ ((row >> 1) & 3)) * 16);
    }

    float acc[2][8][4];
#pragma unroll
    for (int mt = 0; mt < 2; mt++)
#pragma unroll
        for (int nt = 0; nt < 8; nt++)
#pragma unroll
            for (int q = 0; q < 4; q++) acc[mt][nt][q] = 0.f;

    // stage s: A at s*16384, B at s*16384 + 8192
#define LOAD_STAGE(s, kb) do {                                                  \
        const uint32_t st = (uint32_t)(s) * 16384u;                             \
        const int ke = (kb) * 32 + ld_c0 * 8;                                   \
        cp_async16(sb + st + a_soff0,          a_row + ke);                     \
        cp_async16(sb + st + a_soff1,          a_row + ke + 8);                 \
        cp_async16(sb + st + 8192u + a_soff0,  b_row + ke);                     \
        cp_async16(sb + st + 8192u + a_soff1,  b_row + ke + 8);                 \
    } while (0)

    LOAD_STAGE(0, 0); cp_commit();
    LOAD_STAGE(1, 1); cp_commit();

#pragma unroll 1
    for (int kb = 0; kb < NKB; kb++) {
        const int s = kb % 3;
        if (kb + 2 < NKB) {
            LOAD_STAGE((kb + 2) % 3, kb + 2); cp_commit();
            asm volatile("cp.async.wait_group 2;" ::: "memory");
        } else if (kb + 1 < NKB) {
            asm volatile("cp.async.wait_group 1;" ::: "memory");
        } else {
            asm volatile("cp.async.wait_group 0;" ::: "memory");
        }
        __syncthreads();

        const uint32_t sa = sb + (uint32_t)s * 16384u;
        const uint32_t sbB = sa + 8192u;
#pragma unroll
        for (int kk = 0; kk < 2; kk++) {
            const uint32_t kx = kk ? 32u : 0u;
            uint32_t afr[2][4];
#pragma unroll
            for (int mt = 0; mt < 2; mt++) ldsm_x4(afr[mt], sa + (a_off[mt] ^ kx));
            uint32_t bfr[4][4];
#pragma unroll
            for (int bt = 0; bt < 4; bt++) ldsm_x4(bfr[bt], sbB + (b_off[bt] ^ kx));
#pragma unroll
            for (int mt = 0; mt < 2; mt++)
#pragma unroll
                for (int nt = 0; nt < 8; nt++)
                    mma16816(acc[mt][nt], afr[mt], bfr[nt >> 1][(nt & 1) * 2],
                             bfr[nt >> 1][(nt & 1) * 2 + 1]);
        }
        __syncthreads();
    }
#undef LOAD_STAGE

    // ---- epilogue ----
    const int rq = lane >> 2;         // 0..7
    const int cq = (lane & 3) * 2;    // 0,2,4,6
#pragma unroll
    for (int mt = 0; mt < 2; mt++) {
#pragma unroll
        for (int h = 0; h < 2; h++) {
            const int m = warp_m * 32 + mt * 16 + rq + h * 8;
            if (m0 + m >= count) continue;
            const int tok = s_tok[m];
#pragma unroll
            for (int nt = 0; nt < 8; nt++) {
                const int col = warp_n * 64 + nt * 8 + cq;
                float v0 = acc[mt][nt][h * 2 + 0] + bias_t[col];
                float v1 = acc[mt][nt][h * 2 + 1] + bias_t[col + 1];
                if (FIRST) {
                    __half2* dst = (__half2*)(g_hid + (size_t)tok * DH + n0 + col);
                    *dst = __floats2half2_rn(gelu_exact(v0), gelu_exact(v1));
                } else {
                    float2* dst = (float2*)(C_ext + (size_t)tok * DC + n0 + col);
                    *dst = make_float2(v0, v1);
                }
            }
        }
    }
}

// ---------------- host launch ----------------
extern "C" void kernel_launch(void* const* d_in, const int* in_sizes, int n_in,
                              void* d_out, int out_size)
{
    const float* x            = (const float*)d_in[0];
    const float* pe           = (const float*)d_in[1];
    const float* pw           = (const float*)d_in[2];
    const float* cw           = (const float*)d_in[3];
    const float* pos_sigs     = (const float*)d_in[4];
    const float* content_sigs = (const float*)d_in[5];
    const float* W1           = (const float*)d_in[6];
    const float* b1           = (const float*)d_in[7];
    const float* W2           = (const float*)d_in[8];
    const float* b2           = (const float*)d_in[9];
    float* out                = (float*)d_out;

    cudaFuncSetAttribute(grouped_gemm<true>,  cudaFuncAttributeMaxDynamicSharedMemorySize, GG_SMEM);
    cudaFuncSetAttribute(grouped_gemm<false>, cudaFuncAttributeMaxDynamicSharedMemorySize, GG_SMEM);

    zero_counts_kernel<<<1, 32>>>();
    route_kernel<<<NTOK, 128>>>(x, pe, pw, cw, pos_sigs, content_sigs);
    pad_tokens_kernel<<<NTILES, 128>>>();

    convert_x_kernel<<<(NTOK * DC) / (256 * 4), 256>>>(x);
    {   // W1 [1024][4096] -> g_w1h [4096][1024]
        dim3 b(32, 8), g(DH / 32, DC / 32, NTILES);
        convert_w_kernel<<<g, b>>>(W1, DC, DH, 0);
    }
    {   // W2 [4096][1024] -> g_w2h [1024][4096]
        dim3 b(32, 8), g(DC / 32, DH / 32, NTILES);
        convert_w_kernel<<<g, b>>>(W2, DH, DC, 1);
    }

    {   // GEMM1: hidden = gelu(x @ W1 + b1)
        dim3 g(DH / 128, NTOK / 128, NTILES);
        grouped_gemm<true><<<g, 256, GG_SMEM>>>(b1, nullptr);
    }
    {   // GEMM2: out = hidden @ W2 + b2
        dim3 g(DC / 128, NTOK / 128, NTILES);
        grouped_gemm<false><<<g, 256, GG_SMEM>>>(b2, out);
    }
}